// round 14
// baseline (speedup 1.0000x reference)
#include <cuda_runtime.h>
#include <cuda_bf16.h>
#include <cstdint>
#include <cstddef>

#define BATCH   4
#define NV      4096
#define NL      256
#define EMBED   1024
#define HEADS   16
#define HDIM    64
#define LDIM    768
#define BH      (BATCH*HEADS)
#define MV      (BATCH*NV)
#define ML      (BATCH*NL)

// ---------------- scratch ----------------
__device__ float g_qv  [(size_t)MV*2048];    // 128MB: cols [0,1024)=q, [1024,2048)=valv
__device__ float g_kv  [(size_t)ML*2048];    // 8MB:   cols [0,1024)=k, [1024,2048)=vall
__device__ float g_S   [(size_t)BH*NV*NL];
__device__ float g_ov  [(size_t)MV*EMBED];   // tf32-rounded v staging / out_v result
__device__ float g_ol  [(size_t)ML*EMBED];   // tf32-rounded l staging / out_l result
__device__ float g_colm[BH*NL];
__device__ float g_cols[BH*NL];
__device__ float g_pm  [32*BH*NL];
__device__ float g_ps  [32*BH*NL];
__device__ float g_Wt  [5505024];
__device__ __align__(16) uint32_t g_qs[(size_t)BH*NV*64];
__device__ __align__(16) uint32_t g_ks[(size_t)BH*NL*64];

// merged weight layout: [v2q|v2v] rows 0-2047 (K=1024); [l2k|l2v] rows 0-2047 (K=768)
#define WT_V2Q   0
#define WT_V2V   1048576
#define WT_L2K   2097152
#define WT_L2V   2883584
#define WT_V2OUT 3670016
#define WT_L2OUT 4718592

// ---------------- helpers ----------------
__device__ __forceinline__ float tf32_rn(float x) {
    uint32_t r; asm("cvt.rna.tf32.f32 %0, %1;" : "=r"(r) : "f"(x));
    return __uint_as_float(r);
}
__device__ __forceinline__ void mma_tf32(float* c, const uint32_t* a, const uint32_t* b) {
    asm volatile("mma.sync.aligned.m16n8k8.row.col.f32.tf32.tf32.f32 "
        "{%0,%1,%2,%3}, {%4,%5,%6,%7}, {%8,%9}, {%0,%1,%2,%3};"
        : "+f"(c[0]), "+f"(c[1]), "+f"(c[2]), "+f"(c[3])
        : "r"(a[0]), "r"(a[1]), "r"(a[2]), "r"(a[3]), "r"(b[0]), "r"(b[1]));
}
__device__ __forceinline__ void mma_bf16(float* c, const uint32_t* a, uint32_t b0, uint32_t b1) {
    asm volatile("mma.sync.aligned.m16n8k16.row.col.f32.bf16.bf16.f32 "
        "{%0,%1,%2,%3}, {%4,%5,%6,%7}, {%8,%9}, {%0,%1,%2,%3};"
        : "+f"(c[0]), "+f"(c[1]), "+f"(c[2]), "+f"(c[3])
        : "r"(a[0]), "r"(a[1]), "r"(a[2]), "r"(a[3]), "r"(b0), "r"(b1));
}
__device__ __forceinline__ uint32_t pack_bf(float even, float odd) {
    uint32_t r; asm("cvt.rn.bf16x2.f32 %0, %1, %2;" : "=r"(r) : "f"(odd), "f"(even));
    return r;
}
#define HI_EVEN(u) __uint_as_float((u) << 16)
#define HI_ODD(u)  __uint_as_float((u) & 0xffff0000u)

__device__ __forceinline__ uint32_t smem_u32(const void* p) {
    uint32_t a;
    asm("{ .reg .u64 t; cvta.to.shared.u64 t, %1; cvt.u32.u64 %0, t; }" : "=r"(a) : "l"(p));
    return a;
}
__device__ __forceinline__ void ldsm4(uint32_t* r, uint32_t a) {
    asm volatile("ldmatrix.sync.aligned.m8n8.x4.shared.b16 {%0,%1,%2,%3}, [%4];"
        : "=r"(r[0]), "=r"(r[1]), "=r"(r[2]), "=r"(r[3]) : "r"(a));
}
__device__ __forceinline__ void cp16(uint32_t dst, const void* src) {
    asm volatile("cp.async.cg.shared.global [%0], [%1], 16;" :: "r"(dst), "l"(src));
}
#define CP_COMMIT() asm volatile("cp.async.commit_group;" ::: "memory")
#define CP_WAIT(n)  asm volatile("cp.async.wait_group %0;" :: "n"(n) : "memory")

// ---------------- fused weight transposes (emit tf32-rounded) ----------------
struct TP6 { const float* W[6]; float* Wt[6]; int K[6]; int N[6]; };
__global__ void transpose6(TP6 tp)
{
    __shared__ float t[32][33];
    const int id = blockIdx.z;
    const int K = tp.K[id], N = tp.N[id];
    const int kb = blockIdx.y * 32, nb = blockIdx.x * 32;
    if (kb >= K || nb >= N) return;
    const float* W = tp.W[id];
    float* Wt = tp.Wt[id];
    const int x = threadIdx.x, y = threadIdx.y;
    #pragma unroll
    for (int i = 0; i < 32; i += 8)
        t[y + i][x] = W[(size_t)(kb + y + i) * N + nb + x];
    __syncthreads();
    #pragma unroll
    for (int i = 0; i < 32; i += 8)
        Wt[(size_t)(nb + y + i) * K + kb + x] = tf32_rn(t[x][y + i]);
}

// ---------------- elementwise tf32 rounding ----------------
__global__ void round_tf32(const float* __restrict__ src, float* __restrict__ dst)
{
    int i = blockIdx.x * 256 + threadIdx.x;
    float4 x = ((const float4*)src)[i];
    x.x = tf32_rn(x.x); x.y = tf32_rn(x.y); x.z = tf32_rn(x.z); x.w = tf32_rn(x.w);
    ((float4*)dst)[i] = x;
}

// ---------------- split fp32 -> bf16 hi/lo packed planes ----------------
__global__ void split_pack(const float* __restrict__ src, uint32_t* __restrict__ dst,
                           int rowsPerPlane, int rpShift, int srcStride)
{
    int idx = blockIdx.x * 256 + threadIdx.x;
    int quad = idx & 7;
    int R = idx >> 3;
    int p = R >> rpShift;
    int q = R & (rowsPerPlane - 1);
    int b = p >> 4, h = p & 15;
    const float* s = src + ((size_t)(b * rowsPerPlane + q)) * srcStride + h * 64 + quad * 8;
    float4 x0 = *(const float4*)s;
    float4 x1 = *(const float4*)(s + 4);
    uint32_t hi[4], lo[4];
    float e[8] = { x0.x, x0.y, x0.z, x0.w, x1.x, x1.y, x1.z, x1.w };
    #pragma unroll
    for (int i = 0; i < 4; i++) {
        hi[i] = pack_bf(e[2*i], e[2*i+1]);
        lo[i] = pack_bf(e[2*i] - HI_EVEN(hi[i]), e[2*i+1] - HI_ODD(hi[i]));
    }
    uint32_t* d = dst + (size_t)R * 64;
    *(uint4*)(d + quad * 4)      = *(uint4*)hi;
    *(uint4*)(d + 32 + quad * 4) = *(uint4*)lo;
}

// ---------------- tf32 mma.sync GEMM: 3-stage cp.async, 2 CTAs/SM ----------------
// bias covers cols [0,Nhalf), bias2 covers [Nhalf,N).
#define ASTR   36
#define TBUF   (128*ASTR)
#define TBUFB  (TBUF*4)
__global__ __launch_bounds__(256, 2) void mma_gemm(
    const float* __restrict__ A, const float* __restrict__ Bt,
    const float* __restrict__ bias, const float* __restrict__ bias2, int Nhalf,
    float* __restrict__ C, int M, int N, int K)
{
    extern __shared__ float smf[];
    __shared__ float sbias[128];
    const int tid = threadIdx.x, w = tid >> 5, lane = tid & 31;
    const int grp = lane >> 2, tg = lane & 3;
    const int wm = (w & 1) * 64, wn = (w >> 1) * 32;
    const int m0 = blockIdx.y * 128, n0 = blockIdx.x * 128;
    if (tid < 128) {
        int cc = n0 + tid;
        sbias[tid] = (cc < Nhalf) ? bias[cc] : bias2[cc - Nhalf];
    }

    const float* Ab = A + (size_t)m0 * K;
    const float* Bb = Bt + (size_t)n0 * K;
    const int ldr = tid >> 3, ldc = (tid & 7) * 4;

    const uint32_t uA = smem_u32(smf);
    const uint32_t uB = uA + 3 * TBUFB;

    const int arow = ((lane >> 3) & 1) * 8 + (lane & 7);
    const int acol = ((lane >> 4) & 1) * 4;
    const int brow = ((lane >> 4) & 1) * 8 + (lane & 7);
    const int bcol = ((lane >> 3) & 1) * 4;

    float acc[4][4][4];
    #pragma unroll
    for (int i = 0; i < 4; i++)
        #pragma unroll
        for (int j = 0; j < 4; j++)
            #pragma unroll
            for (int t = 0; t < 4; t++) acc[i][j][t] = 0.f;

    const int NC = K / 32;
    #pragma unroll
    for (int pc = 0; pc < 2; pc++) {
        const int k0 = pc * 32;
        #pragma unroll
        for (int i = 0; i < 4; i++) {
            int r = i * 32 + ldr;
            cp16(uA + pc * TBUFB + (r * ASTR + ldc) * 4, Ab + (size_t)r * K + k0 + ldc);
            cp16(uB + pc * TBUFB + (r * ASTR + ldc) * 4, Bb + (size_t)r * K + k0 + ldc);
        }
        CP_COMMIT();
    }

    int sc = 0;
    for (int c = 0; c < NC; c++) {
        if (c + 1 < NC) { CP_WAIT(1); } else { CP_WAIT(0); }
        __syncthreads();
        if (c + 2 < NC) {
            const int sn = (sc >= 1) ? sc - 1 : sc + 2;
            const int k0 = (c + 2) * 32;
            #pragma unroll
            for (int i = 0; i < 4; i++) {
                int r = i * 32 + ldr;
                cp16(uA + sn * TBUFB + (r * ASTR + ldc) * 4, Ab + (size_t)r * K + k0 + ldc);
                cp16(uB + sn * TBUFB + (r * ASTR + ldc) * 4, Bb + (size_t)r * K + k0 + ldc);
            }
            CP_COMMIT();
        }

        const uint32_t uAc = uA + sc * TBUFB;
        const uint32_t uBc = uB + sc * TBUFB;
        #pragma unroll
        for (int s = 0; s < 4; s++) {
            const int k0 = s * 8;
            uint32_t af[4][4], bfr[8];
            #pragma unroll
            for (int i = 0; i < 4; i++)
                ldsm4(af[i], uAc + (((wm + i * 16 + arow) * ASTR) + k0 + acol) * 4);
            #pragma unroll
            for (int jj = 0; jj < 2; jj++)
                ldsm4(&bfr[jj * 4], uBc + (((wn + jj * 16 + brow) * ASTR) + k0 + bcol) * 4);
            #pragma unroll
            for (int i = 0; i < 4; i++)
                #pragma unroll
                for (int j = 0; j < 4; j++)
                    mma_tf32(acc[i][j], af[i], &bfr[j * 2]);
        }
        sc = (sc == 2) ? 0 : sc + 1;
    }

    #pragma unroll
    for (int i = 0; i < 4; i++) {
        int r0 = m0 + wm + i * 16 + grp;
        float* C0 = C + (size_t)r0 * N + n0;
        float* C1 = C + (size_t)(r0 + 8) * N + n0;
        #pragma unroll
        for (int j = 0; j < 4; j++) {
            int cc = wn + j * 8 + 2 * tg;
            float2 v0 = { acc[i][j][0] + sbias[cc], acc[i][j][1] + sbias[cc + 1] };
            float2 v1 = { acc[i][j][2] + sbias[cc], acc[i][j][3] + sbias[cc + 1] };
            *(float2*)(C0 + cc) = v0;
            *(float2*)(C1 + cc) = v1;
        }
    }
}
#define GEMM_SMEM (6 * TBUF * sizeof(float))

// ---------------- scores via bf16x3 mma + fused col-stat partials ----------------
#define SSTR 68
#define SC_SMEM (2*128*SSTR*4 + 4*128*4)
__global__ __launch_bounds__(256, 1) void scores_mma()
{
    extern __shared__ uint32_t su[];
    uint32_t* As = su;
    uint32_t* Bs = su + 128 * SSTR;
    float* red = (float*)(su + 2 * 128 * SSTR);
    const int tid = threadIdx.x, w = tid >> 5, lane = tid & 31;
    const int grp = lane >> 2, tg = lane & 3;
    const int wq = w >> 1, wk = w & 1;
    const int p = blockIdx.z;
    const int q0 = blockIdx.y * 128, k0 = blockIdx.x * 128;

    const uint4* sa = (const uint4*)(g_qs + ((size_t)p * NV + q0) * 64);
    const uint4* sb = (const uint4*)(g_ks + ((size_t)p * NL + k0) * 64);
    #pragma unroll
    for (int i = 0; i < 8; i++) {
        int L = i * 256 + tid;
        int r = L >> 4, c = L & 15;
        *(uint4*)(As + r * SSTR + c * 4) = sa[r * 16 + c];
        *(uint4*)(Bs + r * SSTR + c * 4) = sb[r * 16 + c];
    }
    __syncthreads();

    float acc[2][8][4];
    #pragma unroll
    for (int i = 0; i < 2; i++)
        #pragma unroll
        for (int j = 0; j < 8; j++)
            #pragma unroll
            for (int t = 0; t < 4; t++) acc[i][j][t] = 0.f;

    #pragma unroll
    for (int s = 0; s < 12; s++) {
        const int seg = s >> 2, ss = (s & 3) * 8;
        const int ab = (seg == 2) ? 32 + ss : ss;
        const int bb = (seg == 1) ? 32 + ss : ss;
        uint32_t a[2][4], bf[8][2];
        #pragma unroll
        for (int i = 0; i < 2; i++) {
            int row = wq * 32 + i * 16 + grp;
            a[i][0] = As[row * SSTR + ab + tg];
            a[i][1] = As[(row + 8) * SSTR + ab + tg];
            a[i][2] = As[row * SSTR + ab + 4 + tg];
            a[i][3] = As[(row + 8) * SSTR + ab + 4 + tg];
        }
        #pragma unroll
        for (int j = 0; j < 8; j++) {
            int n = wk * 64 + j * 8 + grp;
            bf[j][0] = Bs[n * SSTR + bb + tg];
            bf[j][1] = Bs[n * SSTR + bb + 4 + tg];
        }
        #pragma unroll
        for (int i = 0; i < 2; i++)
            #pragma unroll
            for (int j = 0; j < 8; j++)
                mma_bf16(acc[i][j], a[i], bf[j][0], bf[j][1]);
    }

    #pragma unroll
    for (int i = 0; i < 2; i++)
        #pragma unroll
        for (int j = 0; j < 8; j++)
            #pragma unroll
            for (int t = 0; t < 4; t++) acc[i][j][t] *= 0.25f;

    #pragma unroll
    for (int i = 0; i < 2; i++)
        #pragma unroll
        for (int h2 = 0; h2 < 2; h2++) {
            int rq = q0 + wq * 32 + i * 16 + grp + h2 * 8;
            float* Sr = g_S + ((size_t)p * NV + rq) * NL + k0 + wk * 64;
            #pragma unroll
            for (int j = 0; j < 8; j++) {
                float2 v = { acc[i][j][h2 * 2], acc[i][j][h2 * 2 + 1] };
                *(float2*)(Sr + j * 8 + 2 * tg) = v;
            }
        }

    float cm[8][2];
    #pragma unroll
    for (int j = 0; j < 8; j++)
        #pragma unroll
        for (int par = 0; par < 2; par++) {
            float m = fmaxf(fmaxf(acc[0][j][par], acc[0][j][2 + par]),
                            fmaxf(acc[1][j][par], acc[1][j][2 + par]));
            #pragma unroll
            for (int o = 4; o <= 16; o <<= 1) m = fmaxf(m, __shfl_xor_sync(0xffffffffu, m, o));
            cm[j][par] = m;
        }
    if (grp == 0)
        #pragma unroll
        for (int j = 0; j < 8; j++)
            #pragma unroll
            for (int par = 0; par < 2; par++)
                red[wq * 128 + wk * 64 + j * 8 + 2 * tg + par] = cm[j][par];
    __syncthreads();
    float tmreg = 0.f;
    if (tid < 128)
        tmreg = fmaxf(fmaxf(red[tid], red[128 + tid]), fmaxf(red[256 + tid], red[384 + tid]));
    __syncthreads();
    if (tid < 128) red[tid] = tmreg;
    __syncthreads();
    float tmv[8][2];
    #pragma unroll
    for (int j = 0; j < 8; j++)
        #pragma unroll
        for (int par = 0; par < 2; par++)
            tmv[j][par] = red[wk * 64 + j * 8 + 2 * tg + par];
    __syncthreads();
    #pragma unroll
    for (int j = 0; j < 8; j++)
        #pragma unroll
        for (int par = 0; par < 2; par++) {
            float s = __expf(acc[0][j][par] - tmv[j][par]) + __expf(acc[0][j][2 + par] - tmv[j][par])
                    + __expf(acc[1][j][par] - tmv[j][par]) + __expf(acc[1][j][2 + par] - tmv[j][par]);
            #pragma unroll
            for (int o = 4; o <= 16; o <<= 1) s += __shfl_xor_sync(0xffffffffu, s, o);
            cm[j][par] = s;
        }
    if (grp == 0)
        #pragma unroll
        for (int j = 0; j < 8; j++)
            #pragma unroll
            for (int par = 0; par < 2; par++)
                red[wq * 128 + wk * 64 + j * 8 + 2 * tg + par] = cm[j][par];
    __syncthreads();
    if (tid < 128) {
        float s = red[tid] + red[128 + tid] + red[256 + tid] + red[384 + tid];
        size_t o = ((size_t)blockIdx.y * BH + p) * NL + k0 + tid;
        g_pm[o] = tmreg;
        g_ps[o] = s;
    }
}

// ---------------- combine partials ----------------
__global__ void colcombine()
{
    const int p = blockIdx.x, col = threadIdx.x;
    float m = -3.0e38f;
    #pragma unroll 8
    for (int t = 0; t < 32; t++)
        m = fmaxf(m, g_pm[((size_t)t * BH + p) * NL + col]);
    float s = 0.f;
    #pragma unroll 8
    for (int t = 0; t < 32; t++) {
        size_t o = ((size_t)t * BH + p) * NL + col;
        s += __expf(g_pm[o] - m) * g_ps[o];
    }
    g_colm[p * NL + col] = m;
    g_cols[p * NL + col] = s;
}

// ---------------- out_v via bf16x3 mma, S tile staged in smem ----------------
#define OVS   0                    // S tile [128][260] floats
#define OV_VH 33280
#define OV_VL 42496
#define OV_MB 51712
#define OV_ST 51968
#define OVM_SMEM (52224 * 4)       // 208896 B
__global__ __launch_bounds__(256, 1) void out_v_mma(const int* __restrict__ mask)
{
    extern __shared__ uint32_t su[];
    float* smf = (float*)su;
    const int bh = blockIdx.y, b = bh >> 4, h = bh & 15;
    const int q0 = blockIdx.x * 128;
    const int tid = threadIdx.x, w = tid >> 5, lane = tid & 31;
    const int grp = lane >> 2, tg = lane & 3;
    const uint32_t uSb = smem_u32(su);

    // async-stage S tile [128][256] -> smem stride 260
    #pragma unroll
    for (int i = 0; i < 32; i++) {
        int idx = i * 256 + tid;
        int row = idx >> 6, c4 = (idx & 63) * 4;
        cp16(uSb + (row * 260 + c4) * 4, g_S + ((size_t)bh * NV + q0 + row) * NL + c4);
    }
    CP_COMMIT();

    smf[OV_MB + tid] = (mask[b * NL + tid] == 0) ? -1.0e9f : 0.0f;
    #pragma unroll
    for (int i = 0; i < 8; i++) {
        int idx = i * 256 + tid;
        int kp = idx >> 4, dg = (idx & 15) * 4;
        const float* v0 = &g_kv[((size_t)(b * NL + 2 * kp)) * 2048 + 1024 + h * 64 + dg];
        float4 A = *(const float4*)v0;
        float4 B = *(const float4*)(v0 + 2048);
        float av[4] = { A.x, A.y, A.z, A.w }, bv[4] = { B.x, B.y, B.z, B.w };
        #pragma unroll
        for (int d = 0; d < 4; d++) {
            uint32_t hi = pack_bf(av[d], bv[d]);
            uint32_t lo = pack_bf(av[d] - HI_EVEN(hi), bv[d] - HI_ODD(hi));
            su[OV_VH + kp * 72 + dg + d] = hi;
            su[OV_VL + kp * 72 + dg + d] = lo;
        }
    }
    CP_WAIT(0);
    __syncthreads();

    for (int r = 0; r < 16; r++) {
        const float* Sr = smf + OVS + (w * 16 + r) * 260;
        float4 s1 = *(const float4*)(Sr + lane * 8);
        float4 s2 = *(const float4*)(Sr + lane * 8 + 4);
        float4 m1 = *(const float4*)&smf[OV_MB + lane * 8];
        float4 m2 = *(const float4*)&smf[OV_MB + lane * 8 + 4];
        float x[8] = { s1.x+m1.x, s1.y+m1.y, s1.z+m1.z, s1.w+m1.w,
                       s2.x+m2.x, s2.y+m2.y, s2.z+m2.z, s2.w+m2.w };
        float m = x[0];
        #pragma unroll
        for (int j = 1; j < 8; j++) m = fmaxf(m, x[j]);
        #pragma unroll
        for (int o = 16; o > 0; o >>= 1) m = fmaxf(m, __shfl_xor_sync(0xffffffffu, m, o));
        float s = 0.f;
        #pragma unroll
        for (int j = 0; j < 8; j++) s += __expf(x[j] - m);
        #pragma unroll
        for (int o = 16; o > 0; o >>= 1) s += __shfl_xor_sync(0xffffffffu, s, o);
        if (lane == 0) { smf[OV_ST + w * 32 + r] = m; smf[OV_ST + w * 32 + 16 + r] = 1.0f / s; }
    }
    __syncwarp();

    const float ma = smf[OV_ST + w * 32 + grp],     ia = smf[OV_ST + w * 32 + 16 + grp];
    const float mb2 = smf[OV_ST + w * 32 + grp + 8], ib = smf[OV_ST + w * 32 + 24 + grp];
    const int Sa = OVS + (w * 16 + grp) * 260;
    const int Sb = Sa + 8 * 260;

    float acc[8][4];
    #pragma unroll
    for (int j = 0; j < 8; j++)
        #pragma unroll
        for (int t = 0; t < 4; t++) acc[j][t] = 0.f;

    for (int c = 0; c < 16; c++) {
        const int ka = c * 16 + 2 * tg, kb = ka + 8;
        float2 mba = *(const float2*)&smf[OV_MB + ka];
        float2 mbb = *(const float2*)&smf[OV_MB + kb];
        float2 s00 = *(const float2*)&smf[Sa + ka], s01 = *(const float2*)&smf[Sa + kb];
        float2 s10 = *(const float2*)&smf[Sb + ka], s11 = *(const float2*)&smf[Sb + kb];
        float e0 = __expf(s00.x + mba.x - ma) * ia, e1 = __expf(s00.y + mba.y - ma) * ia;
        float e2 = __expf(s10.x + mba.x - mb2) * ib, e3 = __expf(s10.y + mba.y - mb2) * ib;
        float e4 = __expf(s01.x + mbb.x - ma) * ia, e5 = __expf(s01.y + mbb.y - ma) * ia;
        float e6 = __expf(s11.x + mbb.x - mb2) * ib, e7 = __expf(s11.y + mbb.y - mb2) * ib;
        uint32_t ah[4], al[4];
        ah[0] = pack_bf(e0, e1); al[0] = pack_bf(e0 - HI_EVEN(ah[0]), e1 - HI_ODD(ah[0]));
        ah[1] = pack_bf(e2, e3); al[1] = pack_bf(e2 - HI_EVEN(ah[1]), e3 - HI_ODD(ah[1]));
        ah[2] = pack_bf(e4, e5); al[2] = pack_bf(e4 - HI_EVEN(ah[2]), e5 - HI_ODD(ah[2]));
        ah[3] = pack_bf(e6, e7); al[3] = pack_bf(e6 - HI_EVEN(ah[3]), e7 - HI_ODD(ah[3]));
        #pragma unroll
        for (int j = 0; j < 8; j++) {
            uint32_t bh0 = su[OV_VH + (c * 8 + tg) * 72 + j * 8 + grp];
            uint32_t bh1 = su[OV_VH + (c * 8 + 4 + tg) * 72 + j * 8 + grp];
            uint32_t bl0 = su[OV_VL + (c * 8 + tg) * 72 + j * 8 + grp];
            uint32_t bl1 = su[OV_VL + (c * 8 + 4 + tg) * 72 + j * 8 + grp];
            mma_bf16(acc[j], ah, bh0, bh1);
            mma_bf16(acc[j], ah, bl0, bl1);
            mma_bf16(acc[j], al, bh0, bh1);
        }
    }
    const int rowa = b * NV + q0 + w * 16 + grp;
    #pragma unroll
    for (int j = 0; j < 8; j++) {
        float2 v0 = { tf32_rn(acc[j][0]), tf32_rn(acc[j][1]) };
        float2 v1 = { tf32_rn(acc[j][2]), tf32_rn(acc[j][3]) };
        *(float2*)&g_ov[(size_t)rowa * EMBED + h * 64 + j * 8 + 2 * tg] = v0;
        *(float2*)&g_ov[(size_t)(rowa + 8) * EMBED + h * 64 + j * 8 + 2 * tg] = v1;
    }
}

// ---------------- out_l via bf16x3 mma ----------------
#define OL_VH 0
#define OL_VL (32*72)
#define OL_SF (2*32*72)
#define OL_CM (OL_SF + 64*132)
#define OL_CI (OL_CM + 128)
#define OLM_SMEM ((OL_CI + 128) * 4)
__global__ __launch_bounds__(256, 1) void out_l_mma()
{
    extern __shared__ uint32_t su[];
    float* smf = (float*)su;
    const int bh = blockIdx.y, b = bh >> 4, h = bh & 15;
    const int k0g = blockIdx.x * 128;
    const int tid = threadIdx.x, w = tid >> 5, lane = tid & 31;
    const int grp = lane >> 2, tg = lane & 3;

    if (tid < 128) {
        smf[OL_CM + tid] = g_colm[bh * NL + k0g + tid];
        smf[OL_CI + tid] = 1.0f / g_cols[bh * NL + k0g + tid];
    }

    float acc[8][4];
    #pragma unroll
    for (int j = 0; j < 8; j++)
        #pragma unroll
        for (int t = 0; t < 4; t++) acc[j][t] = 0.f;

    for (int qc = 0; qc < NV; qc += 64) {
        __syncthreads();
        #pragma unroll
        for (int pss = 0; pss < 8; pss++) {
            int row = pss * 8 + (tid >> 5);
            int col4 = (tid & 31) * 4;
            *(float4*)&smf[OL_SF + row * 132 + col4] =
                *(const float4*)&g_S[((size_t)bh * NV + qc + row) * NL + k0g + col4];
        }
        #pragma unroll
        for (int pss = 0; pss < 2; pss++) {
            int idx = pss * 256 + tid;
            int qp = idx >> 4, dg = (idx & 15) * 4;
            const float* v0 = &g_qv[((size_t)(b * NV + qc + 2 * qp)) * 2048 + 1024 + h * 64 + dg];
            float4 A = *(const float4*)v0;
            float4 B = *(const float4*)(v0 + 2048);
            float av[4] = { A.x, A.y, A.z, A.w }, bv[4] = { B.x, B.y, B.z, B.w };
            #pragma unroll
            for (int d = 0; d < 4; d++) {
                uint32_t hi = pack_bf(av[d], bv[d]);
                uint32_t lo = pack_bf(av[d] - HI_EVEN(hi), bv[d] - HI_ODD(hi));
                su[OL_VH + qp * 72 + dg + d] = hi;
                su[OL_VL + qp * 72 + dg + d] = lo;
            }
        }
        __syncthreads();

        const int ka = w * 16 + grp, kb = ka + 8;
        const float cma = smf[OL_CM + ka], cia = smf[OL_CI + ka];
        const float cmb = smf[OL_CM + kb], cib = smf[OL_CI + kb];
        #pragma unroll
        for (int qs = 0; qs < 4; qs++) {
            const int qa = qs * 16 + 2 * tg;
            float x00 = smf[OL_SF + qa * 132 + ka],       x01 = smf[OL_SF + (qa + 1) * 132 + ka];
            float x10 = smf[OL_SF + qa * 132 + kb],       x11 = smf[OL_SF + (qa + 1) * 132 + kb];
            float x20 = smf[OL_SF + (qa + 8) * 132 + ka], x21 = smf[OL_SF + (qa + 9) * 132 + ka];
            float x30 = smf[OL_SF + (qa + 8) * 132 + kb], x31 = smf[OL_SF + (qa + 9) * 132 + kb];
            float e0 = __expf(x00 - cma) * cia, e1 = __expf(x01 - cma) * cia;
            float e2 = __expf(x10 - cmb) * cib, e3 = __expf(x11 - cmb) * cib;
            float e4 = __expf(x20 - cma) * cia, e5 = __expf(x21 - cma) * cia;
            float e6 = __expf(x30 - cmb) * cib, e7 = __expf(x31 - cmb) * cib;
            uint32_t ah[4], al[4];
            ah[0] = pack_bf(e0, e1); al[0] = pack_bf(e0 - HI_EVEN(ah[0]), e1 - HI_ODD(ah[0]));
            ah[1] = pack_bf(e2, e3); al[1] = pack_bf(e2 - HI_EVEN(ah[1]), e3 - HI_ODD(ah[1]));
            ah[2] = pack_bf(e4, e5); al[2] = pack_bf(e4 - HI_EVEN(ah[2]), e5 - HI_ODD(ah[2]));
            ah[3] = pack_bf(e6, e7); al[3] = pack_bf(e6 - HI_EVEN(ah[3]), e7 - HI_ODD(ah[3]));
            #pragma unroll
            for (int j = 0; j < 8; j++) {
                uint32_t bh0 = su[OL_VH + (qs * 8 + tg) * 72 + j * 8 + grp];
                uint32_t bh1 = su[OL_VH + (qs * 8 + 4 + tg) * 72 + j * 8 + grp];
                uint32_t bl0 = su[OL_VL + (qs * 8 + tg) * 72 + j * 8 + grp];
                uint32_t bl1 = su[OL_VL + (qs * 8 + 4 + tg) * 72 + j * 8 + grp];
                mma_bf16(acc[j], ah, bh0, bh1);
                mma_bf16(acc[j], ah, bl0, bl1);
                mma_bf16(acc[j], al, bh0, bh1);
            }
        }
    }
    const int krow = b * NL + k0g + w * 16 + grp;
    #pragma unroll
    for (int j = 0; j < 8; j++) {
        float2 v0 = { tf32_rn(acc[j][0]), tf32_rn(acc[j][1]) };
        float2 v1 = { tf32_rn(acc[j][2]), tf32_rn(acc[j][3]) };
        *(float2*)&g_ol[(size_t)krow * EMBED + h * 64 + j * 8 + 2 * tg] = v0;
        *(float2*)&g_ol[(size_t)(krow + 8) * EMBED + h * 64 + j * 8 + 2 * tg] = v1;
    }
}

// ---------------- host launcher ----------------
extern "C" void kernel_launch(void* const* d_in, const int* in_sizes, int n_in,
                              void* d_out, int out_size)
{
    (void)in_sizes; (void)n_in; (void)out_size;
    const float* v       = (const float*)d_in[0];
    const float* l       = (const float*)d_in[1];
    const int*   mask    = (const int*)  d_in[2];
    const float* W_v2q   = (const float*)d_in[3];
    const float* b_v2q   = (const float*)d_in[4];
    const float* W_l2k   = (const float*)d_in[5];
    const float* b_l2k   = (const float*)d_in[6];
    const float* W_v2v   = (const float*)d_in[7];
    const float* b_v2v   = (const float*)d_in[8];
    const float* W_l2v   = (const float*)d_in[9];
    const float* b_l2v   = (const float*)d_in[10];
    const float* W_v2out = (const float*)d_in[11];
    const float* b_v2out = (const float*)d_in[12];
    const float* W_l2out = (const float*)d_in[13];
    const float* b_l2out = (const float*)d_in[14];
    float* out = (float*)d_out;

    float *p_qv, *p_kv, *p_ov, *p_ol, *p_wt;
    uint32_t *p_qs, *p_ks;
    cudaGetSymbolAddress((void**)&p_qv, g_qv);
    cudaGetSymbolAddress((void**)&p_kv, g_kv);
    cudaGetSymbolAddress((void**)&p_ov, g_ov);
    cudaGetSymbolAddress((void**)&p_ol, g_ol);
    cudaGetSymbolAddress((void**)&p_wt, g_Wt);
    cudaGetSymbolAddress((void**)&p_qs, g_qs);
    cudaGetSymbolAddress((void**)&p_ks, g_ks);

    static int attr_set = 0;
    if (!attr_set) {
        cudaFuncSetAttribute(mma_gemm,   cudaFuncAttributeMaxDynamicSharedMemorySize, GEMM_SMEM);
        cudaFuncSetAttribute(scores_mma, cudaFuncAttributeMaxDynamicSharedMemorySize, SC_SMEM);
        cudaFuncSetAttribute(out_v_mma,  cudaFuncAttributeMaxDynamicSharedMemorySize, OVM_SMEM);
        cudaFuncSetAttribute(out_l_mma,  cudaFuncAttributeMaxDynamicSharedMemorySize, OLM_SMEM);
        attr_set = 1;
    }

    TP6 tp;
    tp.W[0]=W_v2q;  tp.Wt[0]=p_wt+WT_V2Q;   tp.K[0]=EMBED; tp.N[0]=EMBED;
    tp.W[1]=W_v2v;  tp.Wt[1]=p_wt+WT_V2V;   tp.K[1]=EMBED; tp.N[1]=EMBED;
    tp.W[2]=W_l2k;  tp.Wt[2]=p_wt+WT_L2K;   tp.K[2]=LDIM;  tp.N[2]=EMBED;
    tp.W[3]=W_l2v;  tp.Wt[3]=p_wt+WT_L2V;   tp.K[3]=LDIM;  tp.N[3]=EMBED;
    tp.W[4]=W_v2out;tp.Wt[4]=p_wt+WT_V2OUT; tp.K[4]=EMBED; tp.N[4]=EMBED;
    tp.W[5]=W_l2out;tp.Wt[5]=p_wt+WT_L2OUT; tp.K[5]=EMBED; tp.N[5]=LDIM;
    transpose6<<<dim3(32, 32, 6), dim3(32, 8)>>>(tp);
    round_tf32<<<(MV * EMBED / 4) / 256, 256>>>(v, p_ov);
    round_tf32<<<(ML * LDIM  / 4) / 256, 256>>>(l, p_ol);

    // idx 3: merged vision projection (q|valv), N=2048 — ncu profile window
    mma_gemm<<<dim3(2048/128, MV/128), 256, GEMM_SMEM>>>(p_ov, p_wt+WT_V2Q, b_v2q, b_v2v, 1024, p_qv, MV, 2048, EMBED);
    // idx 4: merged language projection (k|vall)
    mma_gemm<<<dim3(2048/128, ML/128), 256, GEMM_SMEM>>>(p_ol, p_wt+WT_L2K, b_l2k, b_l2v, 1024, p_kv, ML, 2048, LDIM);

    split_pack<<<(BH*NL*8)/256, 256>>>(p_kv, p_ks, NL, 8, 2048);
    split_pack<<<(BH*NV*8)/256, 256>>>(p_qv, p_qs, NV, 12, 2048);
    scores_mma<<<dim3(NL/128, NV/128, BH), 256, SC_SMEM>>>();
    colcombine<<<BH, NL>>>();
    out_v_mma<<<dim3(NV/128, BH), 256, OVM_SMEM>>>(mask);
    out_l_mma<<<dim3(NL/128, BH), 256, OLM_SMEM>>>();
    mma_gemm<<<dim3(EMBED/128, MV/128), 256, GEMM_SMEM>>>(p_ov, p_wt+WT_V2OUT, b_v2out, b_v2out, EMBED, out, MV, EMBED, EMBED);
    mma_gemm<<<dim3(LDIM/128,  ML/128), 256, GEMM_SMEM>>>(p_ol, p_wt+WT_L2OUT, b_l2out, b_l2out, LDIM, out + (size_t)MV*EMBED, ML, LDIM, EMBED);
}

// round 15
// speedup vs baseline: 1.5532x; 1.5532x over previous
#include <cuda_runtime.h>
#include <cuda_bf16.h>
#include <cstdint>
#include <cstddef>

#define BATCH   4
#define NV      4096
#define NL      256
#define EMBED   1024
#define HEADS   16
#define HDIM    64
#define LDIM    768
#define BH      (BATCH*HEADS)
#define MV      (BATCH*NV)
#define ML      (BATCH*NL)

// ---------------- scratch ----------------
__device__ float g_q   [(size_t)MV*EMBED];
__device__ float g_valv[(size_t)MV*EMBED];
__device__ float g_kv  [(size_t)ML*2048];    // cols [0,1024)=k, [1024,2048)=vall
__device__ float g_S   [(size_t)BH*NV*NL];
__device__ float g_ov  [(size_t)MV*EMBED];   // tf32-rounded v staging / out_v result
__device__ float g_ol  [(size_t)ML*EMBED];   // tf32-rounded l staging / out_l result
__device__ float g_colm[BH*NL];
__device__ float g_cols[BH*NL];
__device__ float g_pm  [32*BH*NL];
__device__ float g_ps  [32*BH*NL];
__device__ float g_Wt  [5505024];
__device__ __align__(16) uint32_t g_qs[(size_t)BH*NV*64];
__device__ __align__(16) uint32_t g_ks[(size_t)BH*NL*64];

// weight layout: v2q, v2v separate; [l2k|l2v] merged rows 0-2047 (K=768)
#define WT_V2Q   0
#define WT_V2V   1048576
#define WT_L2K   2097152
#define WT_L2V   2883584
#define WT_V2OUT 3670016
#define WT_L2OUT 4718592

// ---------------- helpers ----------------
__device__ __forceinline__ float tf32_rn(float x) {
    uint32_t r; asm("cvt.rna.tf32.f32 %0, %1;" : "=r"(r) : "f"(x));
    return __uint_as_float(r);
}
__device__ __forceinline__ void mma_tf32(float* c, const uint32_t* a, const uint32_t* b) {
    asm volatile("mma.sync.aligned.m16n8k8.row.col.f32.tf32.tf32.f32 "
        "{%0,%1,%2,%3}, {%4,%5,%6,%7}, {%8,%9}, {%0,%1,%2,%3};"
        : "+f"(c[0]), "+f"(c[1]), "+f"(c[2]), "+f"(c[3])
        : "r"(a[0]), "r"(a[1]), "r"(a[2]), "r"(a[3]), "r"(b[0]), "r"(b[1]));
}
__device__ __forceinline__ void mma_bf16(float* c, const uint32_t* a, uint32_t b0, uint32_t b1) {
    asm volatile("mma.sync.aligned.m16n8k16.row.col.f32.bf16.bf16.f32 "
        "{%0,%1,%2,%3}, {%4,%5,%6,%7}, {%8,%9}, {%0,%1,%2,%3};"
        : "+f"(c[0]), "+f"(c[1]), "+f"(c[2]), "+f"(c[3])
        : "r"(a[0]), "r"(a[1]), "r"(a[2]), "r"(a[3]), "r"(b0), "r"(b1));
}
__device__ __forceinline__ uint32_t pack_bf(float even, float odd) {
    uint32_t r; asm("cvt.rn.bf16x2.f32 %0, %1, %2;" : "=r"(r) : "f"(odd), "f"(even));
    return r;
}
#define HI_EVEN(u) __uint_as_float((u) << 16)
#define HI_ODD(u)  __uint_as_float((u) & 0xffff0000u)

__device__ __forceinline__ uint32_t smem_u32(const void* p) {
    uint32_t a;
    asm("{ .reg .u64 t; cvta.to.shared.u64 t, %1; cvt.u32.u64 %0, t; }" : "=r"(a) : "l"(p));
    return a;
}
__device__ __forceinline__ void ldsm4(uint32_t* r, uint32_t a) {
    asm volatile("ldmatrix.sync.aligned.m8n8.x4.shared.b16 {%0,%1,%2,%3}, [%4];"
        : "=r"(r[0]), "=r"(r[1]), "=r"(r[2]), "=r"(r[3]) : "r"(a));
}
__device__ __forceinline__ void cp16(uint32_t dst, const void* src) {
    asm volatile("cp.async.cg.shared.global [%0], [%1], 16;" :: "r"(dst), "l"(src));
}
#define CP_COMMIT() asm volatile("cp.async.commit_group;" ::: "memory")
#define CP_WAIT(n)  asm volatile("cp.async.wait_group %0;" :: "n"(n) : "memory")

// ---------------- fused weight transposes (emit tf32-rounded) ----------------
struct TP6 { const float* W[6]; float* Wt[6]; int K[6]; int N[6]; };
__global__ void transpose6(TP6 tp)
{
    __shared__ float t[32][33];
    const int id = blockIdx.z;
    const int K = tp.K[id], N = tp.N[id];
    const int kb = blockIdx.y * 32, nb = blockIdx.x * 32;
    if (kb >= K || nb >= N) return;
    const float* W = tp.W[id];
    float* Wt = tp.Wt[id];
    const int x = threadIdx.x, y = threadIdx.y;
    #pragma unroll
    for (int i = 0; i < 32; i += 8)
        t[y + i][x] = W[(size_t)(kb + y + i) * N + nb + x];
    __syncthreads();
    #pragma unroll
    for (int i = 0; i < 32; i += 8)
        Wt[(size_t)(nb + y + i) * K + kb + x] = tf32_rn(t[x][y + i]);
}

// ---------------- elementwise tf32 rounding ----------------
__global__ void round_tf32(const float* __restrict__ src, float* __restrict__ dst)
{
    int i = blockIdx.x * 256 + threadIdx.x;
    float4 x = ((const float4*)src)[i];
    x.x = tf32_rn(x.x); x.y = tf32_rn(x.y); x.z = tf32_rn(x.z); x.w = tf32_rn(x.w);
    ((float4*)dst)[i] = x;
}

// ---------------- split fp32 -> bf16 hi/lo packed planes ----------------
__global__ void split_pack(const float* __restrict__ src, uint32_t* __restrict__ dst,
                           int rowsPerPlane, int rpShift, int srcStride)
{
    int idx = blockIdx.x * 256 + threadIdx.x;
    int quad = idx & 7;
    int R = idx >> 3;
    int p = R >> rpShift;
    int q = R & (rowsPerPlane - 1);
    int b = p >> 4, h = p & 15;
    const float* s = src + ((size_t)(b * rowsPerPlane + q)) * srcStride + h * 64 + quad * 8;
    float4 x0 = *(const float4*)s;
    float4 x1 = *(const float4*)(s + 4);
    uint32_t hi[4], lo[4];
    float e[8] = { x0.x, x0.y, x0.z, x0.w, x1.x, x1.y, x1.z, x1.w };
    #pragma unroll
    for (int i = 0; i < 4; i++) {
        hi[i] = pack_bf(e[2*i], e[2*i+1]);
        lo[i] = pack_bf(e[2*i] - HI_EVEN(hi[i]), e[2*i+1] - HI_ODD(hi[i]));
    }
    uint32_t* d = dst + (size_t)R * 64;
    *(uint4*)(d + quad * 4)      = *(uint4*)hi;
    *(uint4*)(d + 32 + quad * 4) = *(uint4*)lo;
}

// ---------------- tf32 mma.sync GEMM: 3-stage cp.async, 2 CTAs/SM ----------------
// bias covers cols [0,Nhalf), bias2 covers [Nhalf,N).
#define ASTR   36
#define TBUF   (128*ASTR)
#define TBUFB  (TBUF*4)
__global__ __launch_bounds__(256, 2) void mma_gemm(
    const float* __restrict__ A, const float* __restrict__ Bt,
    const float* __restrict__ bias, const float* __restrict__ bias2, int Nhalf,
    float* __restrict__ C, int M, int N, int K)
{
    extern __shared__ float smf[];
    __shared__ float sbias[128];
    const int tid = threadIdx.x, w = tid >> 5, lane = tid & 31;
    const int grp = lane >> 2, tg = lane & 3;
    const int wm = (w & 1) * 64, wn = (w >> 1) * 32;
    const int m0 = blockIdx.y * 128, n0 = blockIdx.x * 128;
    if (tid < 128) {
        int cc = n0 + tid;
        sbias[tid] = (cc < Nhalf) ? bias[cc] : bias2[cc - Nhalf];
    }

    const float* Ab = A + (size_t)m0 * K;
    const float* Bb = Bt + (size_t)n0 * K;
    const int ldr = tid >> 3, ldc = (tid & 7) * 4;

    const uint32_t uA = smem_u32(smf);
    const uint32_t uB = uA + 3 * TBUFB;

    const int arow = ((lane >> 3) & 1) * 8 + (lane & 7);
    const int acol = ((lane >> 4) & 1) * 4;
    const int brow = ((lane >> 4) & 1) * 8 + (lane & 7);
    const int bcol = ((lane >> 3) & 1) * 4;

    float acc[4][4][4];
    #pragma unroll
    for (int i = 0; i < 4; i++)
        #pragma unroll
        for (int j = 0; j < 4; j++)
            #pragma unroll
            for (int t = 0; t < 4; t++) acc[i][j][t] = 0.f;

    const int NC = K / 32;
    #pragma unroll
    for (int pc = 0; pc < 2; pc++) {
        const int k0 = pc * 32;
        #pragma unroll
        for (int i = 0; i < 4; i++) {
            int r = i * 32 + ldr;
            cp16(uA + pc * TBUFB + (r * ASTR + ldc) * 4, Ab + (size_t)r * K + k0 + ldc);
            cp16(uB + pc * TBUFB + (r * ASTR + ldc) * 4, Bb + (size_t)r * K + k0 + ldc);
        }
        CP_COMMIT();
    }

    int sc = 0;
    for (int c = 0; c < NC; c++) {
        if (c + 1 < NC) { CP_WAIT(1); } else { CP_WAIT(0); }
        __syncthreads();
        if (c + 2 < NC) {
            const int sn = (sc >= 1) ? sc - 1 : sc + 2;
            const int k0 = (c + 2) * 32;
            #pragma unroll
            for (int i = 0; i < 4; i++) {
                int r = i * 32 + ldr;
                cp16(uA + sn * TBUFB + (r * ASTR + ldc) * 4, Ab + (size_t)r * K + k0 + ldc);
                cp16(uB + sn * TBUFB + (r * ASTR + ldc) * 4, Bb + (size_t)r * K + k0 + ldc);
            }
            CP_COMMIT();
        }

        const uint32_t uAc = uA + sc * TBUFB;
        const uint32_t uBc = uB + sc * TBUFB;
        #pragma unroll
        for (int s = 0; s < 4; s++) {
            const int k0 = s * 8;
            uint32_t af[4][4], bfr[8];
            #pragma unroll
            for (int i = 0; i < 4; i++)
                ldsm4(af[i], uAc + (((wm + i * 16 + arow) * ASTR) + k0 + acol) * 4);
            #pragma unroll
            for (int jj = 0; jj < 2; jj++)
                ldsm4(&bfr[jj * 4], uBc + (((wn + jj * 16 + brow) * ASTR) + k0 + bcol) * 4);
            #pragma unroll
            for (int i = 0; i < 4; i++)
                #pragma unroll
                for (int j = 0; j < 4; j++)
                    mma_tf32(acc[i][j], af[i], &bfr[j * 2]);
        }
        sc = (sc == 2) ? 0 : sc + 1;
    }

    #pragma unroll
    for (int i = 0; i < 4; i++) {
        int r0 = m0 + wm + i * 16 + grp;
        float* C0 = C + (size_t)r0 * N + n0;
        float* C1 = C + (size_t)(r0 + 8) * N + n0;
        #pragma unroll
        for (int j = 0; j < 4; j++) {
            int cc = wn + j * 8 + 2 * tg;
            float2 v0 = { acc[i][j][0] + sbias[cc], acc[i][j][1] + sbias[cc + 1] };
            float2 v1 = { acc[i][j][2] + sbias[cc], acc[i][j][3] + sbias[cc + 1] };
            *(float2*)(C0 + cc) = v0;
            *(float2*)(C1 + cc) = v1;
        }
    }
}
#define GEMM_SMEM (6 * TBUF * sizeof(float))

// ---------------- scores via bf16x3 mma + fused col-stat partials ----------------
#define SSTR 68
#define SC_SMEM (2*128*SSTR*4 + 4*128*4)
__global__ __launch_bounds__(256, 1) void scores_mma()
{
    extern __shared__ uint32_t su[];
    uint32_t* As = su;
    uint32_t* Bs = su + 128 * SSTR;
    float* red = (float*)(su + 2 * 128 * SSTR);
    const int tid = threadIdx.x, w = tid >> 5, lane = tid & 31;
    const int grp = lane >> 2, tg = lane & 3;
    const int wq = w >> 1, wk = w & 1;
    const int p = blockIdx.z;
    const int q0 = blockIdx.y * 128, k0 = blockIdx.x * 128;

    const uint4* sa = (const uint4*)(g_qs + ((size_t)p * NV + q0) * 64);
    const uint4* sb = (const uint4*)(g_ks + ((size_t)p * NL + k0) * 64);
    #pragma unroll
    for (int i = 0; i < 8; i++) {
        int L = i * 256 + tid;
        int r = L >> 4, c = L & 15;
        *(uint4*)(As + r * SSTR + c * 4) = sa[r * 16 + c];
        *(uint4*)(Bs + r * SSTR + c * 4) = sb[r * 16 + c];
    }
    __syncthreads();

    float acc[2][8][4];
    #pragma unroll
    for (int i = 0; i < 2; i++)
        #pragma unroll
        for (int j = 0; j < 8; j++)
            #pragma unroll
            for (int t = 0; t < 4; t++) acc[i][j][t] = 0.f;

    #pragma unroll
    for (int s = 0; s < 12; s++) {
        const int seg = s >> 2, ss = (s & 3) * 8;
        const int ab = (seg == 2) ? 32 + ss : ss;
        const int bb = (seg == 1) ? 32 + ss : ss;
        uint32_t a[2][4], bf[8][2];
        #pragma unroll
        for (int i = 0; i < 2; i++) {
            int row = wq * 32 + i * 16 + grp;
            a[i][0] = As[row * SSTR + ab + tg];
            a[i][1] = As[(row + 8) * SSTR + ab + tg];
            a[i][2] = As[row * SSTR + ab + 4 + tg];
            a[i][3] = As[(row + 8) * SSTR + ab + 4 + tg];
        }
        #pragma unroll
        for (int j = 0; j < 8; j++) {
            int n = wk * 64 + j * 8 + grp;
            bf[j][0] = Bs[n * SSTR + bb + tg];
            bf[j][1] = Bs[n * SSTR + bb + 4 + tg];
        }
        #pragma unroll
        for (int i = 0; i < 2; i++)
            #pragma unroll
            for (int j = 0; j < 8; j++)
                mma_bf16(acc[i][j], a[i], bf[j][0], bf[j][1]);
    }

    #pragma unroll
    for (int i = 0; i < 2; i++)
        #pragma unroll
        for (int j = 0; j < 8; j++)
            #pragma unroll
            for (int t = 0; t < 4; t++) acc[i][j][t] *= 0.25f;

    #pragma unroll
    for (int i = 0; i < 2; i++)
        #pragma unroll
        for (int h2 = 0; h2 < 2; h2++) {
            int rq = q0 + wq * 32 + i * 16 + grp + h2 * 8;
            float* Sr = g_S + ((size_t)p * NV + rq) * NL + k0 + wk * 64;
            #pragma unroll
            for (int j = 0; j < 8; j++) {
                float2 v = { acc[i][j][h2 * 2], acc[i][j][h2 * 2 + 1] };
                *(float2*)(Sr + j * 8 + 2 * tg) = v;
            }
        }

    float cm[8][2];
    #pragma unroll
    for (int j = 0; j < 8; j++)
        #pragma unroll
        for (int par = 0; par < 2; par++) {
            float m = fmaxf(fmaxf(acc[0][j][par], acc[0][j][2 + par]),
                            fmaxf(acc[1][j][par], acc[1][j][2 + par]));
            #pragma unroll
            for (int o = 4; o <= 16; o <<= 1) m = fmaxf(m, __shfl_xor_sync(0xffffffffu, m, o));
            cm[j][par] = m;
        }
    if (grp == 0)
        #pragma unroll
        for (int j = 0; j < 8; j++)
            #pragma unroll
            for (int par = 0; par < 2; par++)
                red[wq * 128 + wk * 64 + j * 8 + 2 * tg + par] = cm[j][par];
    __syncthreads();
    float tmreg = 0.f;
    if (tid < 128)
        tmreg = fmaxf(fmaxf(red[tid], red[128 + tid]), fmaxf(red[256 + tid], red[384 + tid]));
    __syncthreads();
    if (tid < 128) red[tid] = tmreg;
    __syncthreads();
    float tmv[8][2];
    #pragma unroll
    for (int j = 0; j < 8; j++)
        #pragma unroll
        for (int par = 0; par < 2; par++)
            tmv[j][par] = red[wk * 64 + j * 8 + 2 * tg + par];
    __syncthreads();
    #pragma unroll
    for (int j = 0; j < 8; j++)
        #pragma unroll
        for (int par = 0; par < 2; par++) {
            float s = __expf(acc[0][j][par] - tmv[j][par]) + __expf(acc[0][j][2 + par] - tmv[j][par])
                    + __expf(acc[1][j][par] - tmv[j][par]) + __expf(acc[1][j][2 + par] - tmv[j][par]);
            #pragma unroll
            for (int o = 4; o <= 16; o <<= 1) s += __shfl_xor_sync(0xffffffffu, s, o);
            cm[j][par] = s;
        }
    if (grp == 0)
        #pragma unroll
        for (int j = 0; j < 8; j++)
            #pragma unroll
            for (int par = 0; par < 2; par++)
                red[wq * 128 + wk * 64 + j * 8 + 2 * tg + par] = cm[j][par];
    __syncthreads();
    if (tid < 128) {
        float s = red[tid] + red[128 + tid] + red[256 + tid] + red[384 + tid];
        size_t o = ((size_t)blockIdx.y * BH + p) * NL + k0 + tid;
        g_pm[o] = tmreg;
        g_ps[o] = s;
    }
}

// ---------------- combine partials ----------------
__global__ void colcombine()
{
    const int p = blockIdx.x, col = threadIdx.x;
    float m = -3.0e38f;
    #pragma unroll 8
    for (int t = 0; t < 32; t++)
        m = fmaxf(m, g_pm[((size_t)t * BH + p) * NL + col]);
    float s = 0.f;
    #pragma unroll 8
    for (int t = 0; t < 32; t++) {
        size_t o = ((size_t)t * BH + p) * NL + col;
        s += __expf(g_pm[o] - m) * g_ps[o];
    }
    g_colm[p * NL + col] = m;
    g_cols[p * NL + col] = s;
}

// ---------------- out_v via bf16x3 mma (round-12 version; Vl from g_kv) ----------------
#define OV_VH 0
#define OV_VL (128*72)
#define OV_MB (2*128*72)
#define OV_ST (OV_MB + 256)
#define OVM_SMEM ((OV_ST + 8*32) * 4)
__global__ __launch_bounds__(256, 1) void out_v_mma(const int* __restrict__ mask)
{
    extern __shared__ uint32_t su[];
    float* smf = (float*)su;
    const int bh = blockIdx.y, b = bh >> 4, h = bh & 15;
    const int q0 = blockIdx.x * 128;
    const int tid = threadIdx.x, w = tid >> 5, lane = tid & 31;
    const int grp = lane >> 2, tg = lane & 3;

    smf[OV_MB + tid] = (mask[b * NL + tid] == 0) ? -1.0e9f : 0.0f;
    #pragma unroll
    for (int i = 0; i < 8; i++) {
        int idx = i * 256 + tid;
        int kp = idx >> 4, dg = (idx & 15) * 4;
        const float* v0 = &g_kv[((size_t)(b * NL + 2 * kp)) * 2048 + 1024 + h * 64 + dg];
        float4 A = *(const float4*)v0;
        float4 B = *(const float4*)(v0 + 2048);
        float av[4] = { A.x, A.y, A.z, A.w }, bv[4] = { B.x, B.y, B.z, B.w };
        #pragma unroll
        for (int d = 0; d < 4; d++) {
            uint32_t hi = pack_bf(av[d], bv[d]);
            uint32_t lo = pack_bf(av[d] - HI_EVEN(hi), bv[d] - HI_ODD(hi));
            su[OV_VH + kp * 72 + dg + d] = hi;
            su[OV_VL + kp * 72 + dg + d] = lo;
        }
    }
    __syncthreads();

    for (int r = 0; r < 16; r++) {
        const float* Sr = g_S + ((size_t)bh * NV + q0 + w * 16 + r) * NL;
        float4 s1 = *(const float4*)(Sr + lane * 8);
        float4 s2 = *(const float4*)(Sr + lane * 8 + 4);
        float4 m1 = *(const float4*)&smf[OV_MB + lane * 8];
        float4 m2 = *(const float4*)&smf[OV_MB + lane * 8 + 4];
        float x[8] = { s1.x+m1.x, s1.y+m1.y, s1.z+m1.z, s1.w+m1.w,
                       s2.x+m2.x, s2.y+m2.y, s2.z+m2.z, s2.w+m2.w };
        float m = x[0];
        #pragma unroll
        for (int j = 1; j < 8; j++) m = fmaxf(m, x[j]);
        #pragma unroll
        for (int o = 16; o > 0; o >>= 1) m = fmaxf(m, __shfl_xor_sync(0xffffffffu, m, o));
        float s = 0.f;
        #pragma unroll
        for (int j = 0; j < 8; j++) s += __expf(x[j] - m);
        #pragma unroll
        for (int o = 16; o > 0; o >>= 1) s += __shfl_xor_sync(0xffffffffu, s, o);
        if (lane == 0) { smf[OV_ST + w * 32 + r] = m; smf[OV_ST + w * 32 + 16 + r] = 1.0f / s; }
    }
    __syncwarp();

    const float ma = smf[OV_ST + w * 32 + grp],     ia = smf[OV_ST + w * 32 + 16 + grp];
    const float mb2 = smf[OV_ST + w * 32 + grp + 8], ib = smf[OV_ST + w * 32 + 24 + grp];
    const float* Sa = g_S + ((size_t)bh * NV + q0 + w * 16 + grp) * NL;
    const float* Sb = Sa + 8 * NL;

    float acc[8][4];
    #pragma unroll
    for (int j = 0; j < 8; j++)
        #pragma unroll
        for (int t = 0; t < 4; t++) acc[j][t] = 0.f;

    for (int c = 0; c < 16; c++) {
        const int ka = c * 16 + 2 * tg, kb = ka + 8;
        float2 mba = *(const float2*)&smf[OV_MB + ka];
        float2 mbb = *(const float2*)&smf[OV_MB + kb];
        float2 s00 = *(const float2*)(Sa + ka), s01 = *(const float2*)(Sa + kb);
        float2 s10 = *(const float2*)(Sb + ka), s11 = *(const float2*)(Sb + kb);
        float e0 = __expf(s00.x + mba.x - ma) * ia, e1 = __expf(s00.y + mba.y - ma) * ia;
        float e2 = __expf(s10.x + mba.x - mb2) * ib, e3 = __expf(s10.y + mba.y - mb2) * ib;
        float e4 = __expf(s01.x + mbb.x - ma) * ia, e5 = __expf(s01.y + mbb.y - ma) * ia;
        float e6 = __expf(s11.x + mbb.x - mb2) * ib, e7 = __expf(s11.y + mbb.y - mb2) * ib;
        uint32_t ah[4], al[4];
        ah[0] = pack_bf(e0, e1); al[0] = pack_bf(e0 - HI_EVEN(ah[0]), e1 - HI_ODD(ah[0]));
        ah[1] = pack_bf(e2, e3); al[1] = pack_bf(e2 - HI_EVEN(ah[1]), e3 - HI_ODD(ah[1]));
        ah[2] = pack_bf(e4, e5); al[2] = pack_bf(e4 - HI_EVEN(ah[2]), e5 - HI_ODD(ah[2]));
        ah[3] = pack_bf(e6, e7); al[3] = pack_bf(e6 - HI_EVEN(ah[3]), e7 - HI_ODD(ah[3]));
        #pragma unroll
        for (int j = 0; j < 8; j++) {
            uint32_t bh0 = su[OV_VH + (c * 8 + tg) * 72 + j * 8 + grp];
            uint32_t bh1 = su[OV_VH + (c * 8 + 4 + tg) * 72 + j * 8 + grp];
            uint32_t bl0 = su[OV_VL + (c * 8 + tg) * 72 + j * 8 + grp];
            uint32_t bl1 = su[OV_VL + (c * 8 + 4 + tg) * 72 + j * 8 + grp];
            mma_bf16(acc[j], ah, bh0, bh1);
            mma_bf16(acc[j], ah, bl0, bl1);
            mma_bf16(acc[j], al, bh0, bh1);
        }
    }
    const int rowa = b * NV + q0 + w * 16 + grp;
    #pragma unroll
    for (int j = 0; j < 8; j++) {
        float2 v0 = { tf32_rn(acc[j][0]), tf32_rn(acc[j][1]) };
        float2 v1 = { tf32_rn(acc[j][2]), tf32_rn(acc[j][3]) };
        *(float2*)&g_ov[(size_t)rowa * EMBED + h * 64 + j * 8 + 2 * tg] = v0;
        *(float2*)&g_ov[(size_t)(rowa + 8) * EMBED + h * 64 + j * 8 + 2 * tg] = v1;
    }
}

// ---------------- out_l via bf16x3 mma (round-12 version; Vv from g_valv) ----------------
#define OL_VH 0
#define OL_VL (32*72)
#define OL_SF (2*32*72)
#define OL_CM (OL_SF + 64*132)
#define OL_CI (OL_CM + 128)
#define OLM_SMEM ((OL_CI + 128) * 4)
__global__ __launch_bounds__(256, 1) void out_l_mma()
{
    extern __shared__ uint32_t su[];
    float* smf = (float*)su;
    const int bh = blockIdx.y, b = bh >> 4, h = bh & 15;
    const int k0g = blockIdx.x * 128;
    const int tid = threadIdx.x, w = tid >> 5, lane = tid & 31;
    const int grp = lane >> 2, tg = lane & 3;

    if (tid < 128) {
        smf[OL_CM + tid] = g_colm[bh * NL + k0g + tid];
        smf[OL_CI + tid] = 1.0f / g_cols[bh * NL + k0g + tid];
    }

    float acc[8][4];
    #pragma unroll
    for (int j = 0; j < 8; j++)
        #pragma unroll
        for (int t = 0; t < 4; t++) acc[j][t] = 0.f;

    for (int qc = 0; qc < NV; qc += 64) {
        __syncthreads();
        #pragma unroll
        for (int pss = 0; pss < 8; pss++) {
            int row = pss * 8 + (tid >> 5);
            int col4 = (tid & 31) * 4;
            *(float4*)&smf[OL_SF + row * 132 + col4] =
                *(const float4*)&g_S[((size_t)bh * NV + qc + row) * NL + k0g + col4];
        }
        #pragma unroll
        for (int pss = 0; pss < 2; pss++) {
            int idx = pss * 256 + tid;
            int qp = idx >> 4, dg = (idx & 15) * 4;
            const float* v0 = &g_valv[((size_t)(b * NV + qc + 2 * qp)) * EMBED + h * 64 + dg];
            float4 A = *(const float4*)v0;
            float4 B = *(const float4*)(v0 + EMBED);
            float av[4] = { A.x, A.y, A.z, A.w }, bv[4] = { B.x, B.y, B.z, B.w };
            #pragma unroll
            for (int d = 0; d < 4; d++) {
                uint32_t hi = pack_bf(av[d], bv[d]);
                uint32_t lo = pack_bf(av[d] - HI_EVEN(hi), bv[d] - HI_ODD(hi));
                su[OL_VH + qp * 72 + dg + d] = hi;
                su[OL_VL + qp * 72 + dg + d] = lo;
            }
        }
        __syncthreads();

        const int ka = w * 16 + grp, kb = ka + 8;
        const float cma = smf[OL_CM + ka], cia = smf[OL_CI + ka];
        const float cmb = smf[OL_CM + kb], cib = smf[OL_CI + kb];
        #pragma unroll
        for (int qs = 0; qs < 4; qs++) {
            const int qa = qs * 16 + 2 * tg;
            float x00 = smf[OL_SF + qa * 132 + ka],       x01 = smf[OL_SF + (qa + 1) * 132 + ka];
            float x10 = smf[OL_SF + qa * 132 + kb],       x11 = smf[OL_SF + (qa + 1) * 132 + kb];
            float x20 = smf[OL_SF + (qa + 8) * 132 + ka], x21 = smf[OL_SF + (qa + 9) * 132 + ka];
            float x30 = smf[OL_SF + (qa + 8) * 132 + kb], x31 = smf[OL_SF + (qa + 9) * 132 + kb];
            float e0 = __expf(x00 - cma) * cia, e1 = __expf(x01 - cma) * cia;
            float e2 = __expf(x10 - cmb) * cib, e3 = __expf(x11 - cmb) * cib;
            float e4 = __expf(x20 - cma) * cia, e5 = __expf(x21 - cma) * cia;
            float e6 = __expf(x30 - cmb) * cib, e7 = __expf(x31 - cmb) * cib;
            uint32_t ah[4], al[4];
            ah[0] = pack_bf(e0, e1); al[0] = pack_bf(e0 - HI_EVEN(ah[0]), e1 - HI_ODD(ah[0]));
            ah[1] = pack_bf(e2, e3); al[1] = pack_bf(e2 - HI_EVEN(ah[1]), e3 - HI_ODD(ah[1]));
            ah[2] = pack_bf(e4, e5); al[2] = pack_bf(e4 - HI_EVEN(ah[2]), e5 - HI_ODD(ah[2]));
            ah[3] = pack_bf(e6, e7); al[3] = pack_bf(e6 - HI_EVEN(ah[3]), e7 - HI_ODD(ah[3]));
            #pragma unroll
            for (int j = 0; j < 8; j++) {
                uint32_t bh0 = su[OL_VH + (qs * 8 + tg) * 72 + j * 8 + grp];
                uint32_t bh1 = su[OL_VH + (qs * 8 + 4 + tg) * 72 + j * 8 + grp];
                uint32_t bl0 = su[OL_VL + (qs * 8 + tg) * 72 + j * 8 + grp];
                uint32_t bl1 = su[OL_VL + (qs * 8 + 4 + tg) * 72 + j * 8 + grp];
                mma_bf16(acc[j], ah, bh0, bh1);
                mma_bf16(acc[j], ah, bl0, bl1);
                mma_bf16(acc[j], al, bh0, bh1);
            }
        }
    }
    const int krow = b * NL + k0g + w * 16 + grp;
    #pragma unroll
    for (int j = 0; j < 8; j++) {
        float2 v0 = { tf32_rn(acc[j][0]), tf32_rn(acc[j][1]) };
        float2 v1 = { tf32_rn(acc[j][2]), tf32_rn(acc[j][3]) };
        *(float2*)&g_ol[(size_t)krow * EMBED + h * 64 + j * 8 + 2 * tg] = v0;
        *(float2*)&g_ol[(size_t)(krow + 8) * EMBED + h * 64 + j * 8 + 2 * tg] = v1;
    }
}

// ---------------- host launcher ----------------
extern "C" void kernel_launch(void* const* d_in, const int* in_sizes, int n_in,
                              void* d_out, int out_size)
{
    (void)in_sizes; (void)n_in; (void)out_size;
    const float* v       = (const float*)d_in[0];
    const float* l       = (const float*)d_in[1];
    const int*   mask    = (const int*)  d_in[2];
    const float* W_v2q   = (const float*)d_in[3];
    const float* b_v2q   = (const float*)d_in[4];
    const float* W_l2k   = (const float*)d_in[5];
    const float* b_l2k   = (const float*)d_in[6];
    const float* W_v2v   = (const float*)d_in[7];
    const float* b_v2v   = (const float*)d_in[8];
    const float* W_l2v   = (const float*)d_in[9];
    const float* b_l2v   = (const float*)d_in[10];
    const float* W_v2out = (const float*)d_in[11];
    const float* b_v2out = (const float*)d_in[12];
    const float* W_l2out = (const float*)d_in[13];
    const float* b_l2out = (const float*)d_in[14];
    float* out = (float*)d_out;

    float *p_q, *p_valv, *p_kv, *p_ov, *p_ol, *p_wt;
    uint32_t *p_qs, *p_ks;
    cudaGetSymbolAddress((void**)&p_q,    g_q);
    cudaGetSymbolAddress((void**)&p_valv, g_valv);
    cudaGetSymbolAddress((void**)&p_kv,   g_kv);
    cudaGetSymbolAddress((void**)&p_ov,   g_ov);
    cudaGetSymbolAddress((void**)&p_ol,   g_ol);
    cudaGetSymbolAddress((void**)&p_wt,   g_Wt);
    cudaGetSymbolAddress((void**)&p_qs,   g_qs);
    cudaGetSymbolAddress((void**)&p_ks,   g_ks);

    static int attr_set = 0;
    if (!attr_set) {
        cudaFuncSetAttribute(mma_gemm,   cudaFuncAttributeMaxDynamicSharedMemorySize, GEMM_SMEM);
        cudaFuncSetAttribute(scores_mma, cudaFuncAttributeMaxDynamicSharedMemorySize, SC_SMEM);
        cudaFuncSetAttribute(out_v_mma,  cudaFuncAttributeMaxDynamicSharedMemorySize, OVM_SMEM);
        cudaFuncSetAttribute(out_l_mma,  cudaFuncAttributeMaxDynamicSharedMemorySize, OLM_SMEM);
        attr_set = 1;
    }

    TP6 tp;
    tp.W[0]=W_v2q;  tp.Wt[0]=p_wt+WT_V2Q;   tp.K[0]=EMBED; tp.N[0]=EMBED;
    tp.W[1]=W_v2v;  tp.Wt[1]=p_wt+WT_V2V;   tp.K[1]=EMBED; tp.N[1]=EMBED;
    tp.W[2]=W_l2k;  tp.Wt[2]=p_wt+WT_L2K;   tp.K[2]=LDIM;  tp.N[2]=EMBED;
    tp.W[3]=W_l2v;  tp.Wt[3]=p_wt+WT_L2V;   tp.K[3]=LDIM;  tp.N[3]=EMBED;
    tp.W[4]=W_v2out;tp.Wt[4]=p_wt+WT_V2OUT; tp.K[4]=EMBED; tp.N[4]=EMBED;
    tp.W[5]=W_l2out;tp.Wt[5]=p_wt+WT_L2OUT; tp.K[5]=EMBED; tp.N[5]=LDIM;
    transpose6<<<dim3(32, 32, 6), dim3(32, 8)>>>(tp);
    round_tf32<<<(MV * EMBED / 4) / 256, 256>>>(v, p_ov);
    round_tf32<<<(ML * LDIM  / 4) / 256, 256>>>(l, p_ol);

    // idx 3-4: vision projections SEPARATE (round-12 config; idx 3 = ncu window)
    mma_gemm<<<dim3(EMBED/128, MV/128), 256, GEMM_SMEM>>>(p_ov, p_wt+WT_V2Q, b_v2q, b_v2q, EMBED, p_q,    MV, EMBED, EMBED);
    mma_gemm<<<dim3(EMBED/128, MV/128), 256, GEMM_SMEM>>>(p_ov, p_wt+WT_V2V, b_v2v, b_v2v, EMBED, p_valv, MV, EMBED, EMBED);
    // idx 5: language projections MERGED (k|vall), N=2048
    mma_gemm<<<dim3(2048/128, ML/128), 256, GEMM_SMEM>>>(p_ol, p_wt+WT_L2K, b_l2k, b_l2v, 1024, p_kv, ML, 2048, LDIM);

    split_pack<<<(BH*NL*8)/256, 256>>>(p_kv, p_ks, NL, 8, 2048);
    split_pack<<<(BH*NV*8)/256, 256>>>(p_q,  p_qs, NV, 12, 1024);
    scores_mma<<<dim3(NL/128, NV/128, BH), 256, SC_SMEM>>>();
    colcombine<<<BH, NL>>>();
    out_v_mma<<<dim3(NV/128, BH), 256, OVM_SMEM>>>(mask);
    out_l_mma<<<dim3(NL/128, BH), 256, OLM_SMEM>>>();
    mma_gemm<<<dim3(EMBED/128, MV/128), 256, GEMM_SMEM>>>(p_ov, p_wt+WT_V2OUT, b_v2out, b_v2out, EMBED, out, MV, EMBED, EMBED);
    mma_gemm<<<dim3(LDIM/128,  ML/128), 256, GEMM_SMEM>>>(p_ol, p_wt+WT_L2OUT, b_l2out, b_l2out, LDIM, out + (size_t)MV*EMBED, ML, LDIM, EMBED);
}